// round 7
// baseline (speedup 1.0000x reference)
#include <cuda_runtime.h>
#include <cstdint>

#define Bdim 4
#define Hdim 32
#define Tdim 2048
#define Kdim 64
#define Vdim 64
#define CHUNK 16
#define NCHUNK (Tdim / CHUNK)
#define CHUNK_BYTES (CHUNK * Kdim * 4)   // 4096 B per tensor per chunk

// ---- packed f32x2 helpers (sm_103a FFMA2 path, PTX-only) ----
__device__ __forceinline__ float2 fma2(float2 a, float2 b, float2 c) {
    float2 d;
    asm("fma.rn.f32x2 %0, %1, %2, %3;"
        : "=l"(reinterpret_cast<unsigned long long&>(d))
        : "l"(reinterpret_cast<unsigned long long&>(a)),
          "l"(reinterpret_cast<unsigned long long&>(b)),
          "l"(reinterpret_cast<unsigned long long&>(c)));
    return d;
}
__device__ __forceinline__ float2 mul2(float2 a, float2 b) {
    float2 d;
    asm("mul.rn.f32x2 %0, %1, %2;"
        : "=l"(reinterpret_cast<unsigned long long&>(d))
        : "l"(reinterpret_cast<unsigned long long&>(a)),
          "l"(reinterpret_cast<unsigned long long&>(b)));
    return d;
}
__device__ __forceinline__ float2 add2(float2 a, float2 b) {
    float2 d;
    asm("add.rn.f32x2 %0, %1, %2;"
        : "=l"(reinterpret_cast<unsigned long long&>(d))
        : "l"(reinterpret_cast<unsigned long long&>(a)),
          "l"(reinterpret_cast<unsigned long long&>(b)));
    return d;
}

__device__ __forceinline__ void cp16(uint32_t smem_dst, const void* gmem_src) {
    asm volatile("cp.async.cg.shared.global [%0], [%1], 16;"
                 :: "r"(smem_dst), "l"(gmem_src));
}

// Block = one (b,h). 256 threads: vcol = tid>>2 (0..63), ks = tid&3 (K split 4x16).
// State S[k][v]: each thread holds its 16-k slice of its v-column as 8 packed float2.
// Per step: o_v = sum_k q_k*S_kv + v_v*(sum_k q_k*u_k*k_k);  S = S*exp(w) + k*v.
__global__ __launch_bounds__(256, 1)
void rwkv6_scan_kernel(const float* __restrict__ r,
                       const float* __restrict__ kin,
                       const float* __restrict__ vin,
                       const float* __restrict__ win,
                       const float* __restrict__ uin,
                       const float* __restrict__ h0,
                       float* __restrict__ o,
                       float* __restrict__ hT) {
    const int bh    = blockIdx.x;
    const int h     = bh % Hdim;
    const int tid   = threadIdx.x;
    const int vcol  = tid >> 2;
    const int ks    = tid & 3;
    const int kbase = ks * 16;

    __shared__ float sq[2][CHUNK][Kdim];
    __shared__ float sk[2][CHUNK][Kdim];
    __shared__ float sw[2][CHUNK][Kdim];   // exp() applied in place per chunk
    __shared__ float sv[2][CHUNK][Vdim];
    __shared__ float squk[2][CHUNK];       // per-step  sum_k q*u*k
    __shared__ float su[Kdim];

    // state slice: pair j holds k = kbase+2j, kbase+2j+1
    float2 s2[8];
    {
        const size_t hb = (size_t)bh * Kdim * Vdim;
#pragma unroll
        for (int j = 0; j < 8; j++) {
            s2[j].x = h0[hb + (size_t)(kbase + 2 * j)     * Vdim + vcol];
            s2[j].y = h0[hb + (size_t)(kbase + 2 * j + 1) * Vdim + vcol];
        }
    }
    if (tid < Kdim) su[tid] = uin[h * Kdim + tid];

    const size_t base = (size_t)bh * Tdim * Kdim;   // also valid for v and o (K==V)

    const uint32_t sq_s = (uint32_t)__cvta_generic_to_shared(&sq[0][0][0]);
    const uint32_t sk_s = (uint32_t)__cvta_generic_to_shared(&sk[0][0][0]);
    const uint32_t sw_s = (uint32_t)__cvta_generic_to_shared(&sw[0][0][0]);
    const uint32_t sv_s = (uint32_t)__cvta_generic_to_shared(&sv[0][0][0]);

    // issue a chunk's 4 tensors as one cp.async group into buffer `buf`
    auto issue_chunk = [&](int c, int buf) {
        const size_t off = base + (size_t)c * CHUNK * Kdim;
        const uint32_t bofs = buf * CHUNK_BYTES + tid * 16;
        cp16(sq_s + bofs, r   + off + tid * 4);
        cp16(sk_s + bofs, kin + off + tid * 4);
        cp16(sw_s + bofs, win + off + tid * 4);
        cp16(sv_s + bofs, vin + off + tid * 4);
        asm volatile("cp.async.commit_group;");
    };

    issue_chunk(0, 0);
    issue_chunk(1, 1);

    for (int c = 0; c < NCHUNK; c++) {
        const int cur = c & 1;
        asm volatile("cp.async.wait_group 1;");
        __syncthreads();

        // ---- per-chunk preprocessing ----
        // exp(w) in place: 1024 values / 256 threads = one float4 each
        {
            float4* wf = (float4*)&sw[cur][0][0];
            float4 t = wf[tid];
            t.x = __expf(t.x); t.y = __expf(t.y);
            t.z = __expf(t.z); t.w = __expf(t.w);
            wf[tid] = t;
        }
        // quk[t] = sum_k q*u*k : 16 steps x 16 threads, 4 k's each
        {
            const int stp  = tid >> 4;
            const int part = tid & 15;
            const float* qq = &sq[cur][stp][part * 4];
            const float* kk = &sk[cur][stp][part * 4];
            const float* uu = &su[part * 4];
            float sum = 0.f;
#pragma unroll
            for (int i = 0; i < 4; i++)
                sum = fmaf(qq[i] * kk[i], uu[i], sum);
            sum += __shfl_xor_sync(0xffffffffu, sum, 1);
            sum += __shfl_xor_sync(0xffffffffu, sum, 2);
            sum += __shfl_xor_sync(0xffffffffu, sum, 4);
            sum += __shfl_xor_sync(0xffffffffu, sum, 8);
            if (part == 0) squk[cur][stp] = sum;
        }
        __syncthreads();

        // ---- compute 16 steps, no barriers ----
        const size_t obase = base + (size_t)c * CHUNK * Vdim;
#pragma unroll 4
        for (int tt = 0; tt < CHUNK; tt++) {
            const float4* q4 = (const float4*)&sq[cur][tt][kbase];
            const float4* k4 = (const float4*)&sk[cur][tt][kbase];
            const float4* e4 = (const float4*)&sw[cur][tt][kbase];
            const float myv = sv[cur][tt][vcol];
            const float2 vv = make_float2(myv, myv);

            float2 a0 = make_float2(0.f, 0.f), a1 = a0, a2 = a0, a3 = a0;
#pragma unroll
            for (int jj = 0; jj < 4; jj++) {
                const float4 qa = q4[jj];
                const float4 ka = k4[jj];
                const float4 ea = e4[jj];
                const float2 kvlo = mul2(make_float2(ka.x, ka.y), vv);
                const float2 kvhi = mul2(make_float2(ka.z, ka.w), vv);
                float2& alo = (jj == 0) ? a0 : (jj == 1) ? a1 : (jj == 2) ? a2 : a3;
                alo = fma2(make_float2(qa.x, qa.y), s2[2 * jj], alo);
                s2[2 * jj]     = fma2(s2[2 * jj],     make_float2(ea.x, ea.y), kvlo);
                alo = fma2(make_float2(qa.z, qa.w), s2[2 * jj + 1], alo);
                s2[2 * jj + 1] = fma2(s2[2 * jj + 1], make_float2(ea.z, ea.w), kvhi);
            }
            const float2 asum = add2(add2(a0, a1), add2(a2, a3));
            float acc = asum.x + asum.y;
            acc += __shfl_xor_sync(0xffffffffu, acc, 1);
            acc += __shfl_xor_sync(0xffffffffu, acc, 2);
            if (ks == 0)
                o[obase + (size_t)tt * Vdim + vcol] = fmaf(squk[cur][tt], myv, acc);
        }
        __syncthreads();   // all reads of `cur` done before refill

        if (c + 2 < NCHUNK)
            issue_chunk(c + 2, cur);
    }

    // final state: layout (B,H,K,V)
    {
        const size_t hb = (size_t)bh * Kdim * Vdim;
#pragma unroll
        for (int j = 0; j < 8; j++) {
            hT[hb + (size_t)(kbase + 2 * j)     * Vdim + vcol] = s2[j].x;
            hT[hb + (size_t)(kbase + 2 * j + 1) * Vdim + vcol] = s2[j].y;
        }
    }
}

extern "C" void kernel_launch(void* const* d_in, const int* in_sizes, int n_in,
                              void* d_out, int out_size) {
    const float* r  = (const float*)d_in[0];
    const float* k  = (const float*)d_in[1];
    const float* v  = (const float*)d_in[2];
    const float* w  = (const float*)d_in[3];
    const float* u  = (const float*)d_in[4];
    const float* h0 = (const float*)d_in[5];

    float* o  = (float*)d_out;
    float* hT = o + (size_t)Bdim * Hdim * Tdim * Vdim;

    rwkv6_scan_kernel<<<Bdim * Hdim, 256>>>(r, k, v, w, u, h0, o, hT);
}

// round 8
// speedup vs baseline: 1.0023x; 1.0023x over previous
#include <cuda_runtime.h>
#include <cstdint>

#define Bdim 4
#define Hdim 32
#define Tdim 2048
#define Kdim 64
#define Vdim 64
#define CHUNK 16
#define NCHUNK (Tdim / CHUNK)
#define CHUNK_BYTES (CHUNK * Kdim * 4)   // 4096 B per tensor per chunk

// ---- packed f32x2 helpers (sm_103a FFMA2 path, PTX-only) ----
__device__ __forceinline__ float2 fma2(float2 a, float2 b, float2 c) {
    float2 d;
    asm("fma.rn.f32x2 %0, %1, %2, %3;"
        : "=l"(reinterpret_cast<unsigned long long&>(d))
        : "l"(reinterpret_cast<unsigned long long&>(a)),
          "l"(reinterpret_cast<unsigned long long&>(b)),
          "l"(reinterpret_cast<unsigned long long&>(c)));
    return d;
}
__device__ __forceinline__ float2 mul2(float2 a, float2 b) {
    float2 d;
    asm("mul.rn.f32x2 %0, %1, %2;"
        : "=l"(reinterpret_cast<unsigned long long&>(d))
        : "l"(reinterpret_cast<unsigned long long&>(a)),
          "l"(reinterpret_cast<unsigned long long&>(b)));
    return d;
}
__device__ __forceinline__ float2 add2(float2 a, float2 b) {
    float2 d;
    asm("add.rn.f32x2 %0, %1, %2;"
        : "=l"(reinterpret_cast<unsigned long long&>(d))
        : "l"(reinterpret_cast<unsigned long long&>(a)),
          "l"(reinterpret_cast<unsigned long long&>(b)));
    return d;
}

__device__ __forceinline__ void cp16(uint32_t smem_dst, const void* gmem_src) {
    asm volatile("cp.async.cg.shared.global [%0], [%1], 16;"
                 :: "r"(smem_dst), "l"(gmem_src));
}

// Block = one (b,h). 256 threads: vcol = tid>>2 (0..63), ks = tid&3 (K split 4x16).
// State S[k][v]: each thread holds its 16-k slice of its v-column as 8 packed float2.
// Per step: o_v = sum_k q_k*S_kv + v_v*(sum_k q_k*u_k*k_k);  S = S*exp(w) + k*v.
__global__ __launch_bounds__(256, 1)
void rwkv6_scan_kernel(const float* __restrict__ r,
                       const float* __restrict__ kin,
                       const float* __restrict__ vin,
                       const float* __restrict__ win,
                       const float* __restrict__ uin,
                       const float* __restrict__ h0,
                       float* __restrict__ o,
                       float* __restrict__ hT) {
    const int bh    = blockIdx.x;
    const int h     = bh % Hdim;
    const int tid   = threadIdx.x;
    const int vcol  = tid >> 2;
    const int ks    = tid & 3;
    const int kbase = ks * 16;

    __shared__ float sq[2][CHUNK][Kdim];
    __shared__ float sk[2][CHUNK][Kdim];
    __shared__ float sw[2][CHUNK][Kdim];   // exp() applied in place per chunk
    __shared__ float sv[2][CHUNK][Vdim];
    __shared__ float squk[2][CHUNK];       // per-step  sum_k q*u*k
    __shared__ float su[Kdim];

    // state slice: pair j holds k = kbase+2j, kbase+2j+1
    float2 s2[8];
    {
        const size_t hb = (size_t)bh * Kdim * Vdim;
#pragma unroll
        for (int j = 0; j < 8; j++) {
            s2[j].x = h0[hb + (size_t)(kbase + 2 * j)     * Vdim + vcol];
            s2[j].y = h0[hb + (size_t)(kbase + 2 * j + 1) * Vdim + vcol];
        }
    }
    if (tid < Kdim) su[tid] = uin[h * Kdim + tid];

    const size_t base = (size_t)bh * Tdim * Kdim;   // also valid for v and o (K==V)

    const uint32_t sq_s = (uint32_t)__cvta_generic_to_shared(&sq[0][0][0]);
    const uint32_t sk_s = (uint32_t)__cvta_generic_to_shared(&sk[0][0][0]);
    const uint32_t sw_s = (uint32_t)__cvta_generic_to_shared(&sw[0][0][0]);
    const uint32_t sv_s = (uint32_t)__cvta_generic_to_shared(&sv[0][0][0]);

    // issue a chunk's 4 tensors as one cp.async group into buffer `buf`
    auto issue_chunk = [&](int c, int buf) {
        const size_t off = base + (size_t)c * CHUNK * Kdim;
        const uint32_t bofs = buf * CHUNK_BYTES + tid * 16;
        cp16(sq_s + bofs, r   + off + tid * 4);
        cp16(sk_s + bofs, kin + off + tid * 4);
        cp16(sw_s + bofs, win + off + tid * 4);
        cp16(sv_s + bofs, vin + off + tid * 4);
        asm volatile("cp.async.commit_group;");
    };

    issue_chunk(0, 0);
    issue_chunk(1, 1);

    for (int c = 0; c < NCHUNK; c++) {
        const int cur = c & 1;
        asm volatile("cp.async.wait_group 1;");
        __syncthreads();

        // ---- per-chunk preprocessing ----
        // exp(w) in place: 1024 values / 256 threads = one float4 each
        {
            float4* wf = (float4*)&sw[cur][0][0];
            float4 t = wf[tid];
            t.x = __expf(t.x); t.y = __expf(t.y);
            t.z = __expf(t.z); t.w = __expf(t.w);
            wf[tid] = t;
        }
        // quk[t] = sum_k q*u*k : 16 steps x 16 threads, 4 k's each
        {
            const int stp  = tid >> 4;
            const int part = tid & 15;
            const float* qq = &sq[cur][stp][part * 4];
            const float* kk = &sk[cur][stp][part * 4];
            const float* uu = &su[part * 4];
            float sum = 0.f;
#pragma unroll
            for (int i = 0; i < 4; i++)
                sum = fmaf(qq[i] * kk[i], uu[i], sum);
            sum += __shfl_xor_sync(0xffffffffu, sum, 1);
            sum += __shfl_xor_sync(0xffffffffu, sum, 2);
            sum += __shfl_xor_sync(0xffffffffu, sum, 4);
            sum += __shfl_xor_sync(0xffffffffu, sum, 8);
            if (part == 0) squk[cur][stp] = sum;
        }
        __syncthreads();

        // ---- compute 16 steps, no barriers ----
        const size_t obase = base + (size_t)c * CHUNK * Vdim;
#pragma unroll 4
        for (int tt = 0; tt < CHUNK; tt++) {
            const float4* q4 = (const float4*)&sq[cur][tt][kbase];
            const float4* k4 = (const float4*)&sk[cur][tt][kbase];
            const float4* e4 = (const float4*)&sw[cur][tt][kbase];
            const float myv = sv[cur][tt][vcol];
            const float2 vv = make_float2(myv, myv);

            float2 a0 = make_float2(0.f, 0.f), a1 = a0, a2 = a0, a3 = a0;
#pragma unroll
            for (int jj = 0; jj < 4; jj++) {
                const float4 qa = q4[jj];
                const float4 ka = k4[jj];
                const float4 ea = e4[jj];
                const float2 kvlo = mul2(make_float2(ka.x, ka.y), vv);
                const float2 kvhi = mul2(make_float2(ka.z, ka.w), vv);
                float2& alo = (jj == 0) ? a0 : (jj == 1) ? a1 : (jj == 2) ? a2 : a3;
                alo = fma2(make_float2(qa.x, qa.y), s2[2 * jj], alo);
                s2[2 * jj]     = fma2(s2[2 * jj],     make_float2(ea.x, ea.y), kvlo);
                alo = fma2(make_float2(qa.z, qa.w), s2[2 * jj + 1], alo);
                s2[2 * jj + 1] = fma2(s2[2 * jj + 1], make_float2(ea.z, ea.w), kvhi);
            }
            const float2 asum = add2(add2(a0, a1), add2(a2, a3));
            float acc = asum.x + asum.y;
            acc += __shfl_xor_sync(0xffffffffu, acc, 1);
            acc += __shfl_xor_sync(0xffffffffu, acc, 2);
            if (ks == 0)
                o[obase + (size_t)tt * Vdim + vcol] = fmaf(squk[cur][tt], myv, acc);
        }
        __syncthreads();   // all reads of `cur` done before refill

        if (c + 2 < NCHUNK)
            issue_chunk(c + 2, cur);
    }

    // final state: layout (B,H,K,V)
    {
        const size_t hb = (size_t)bh * Kdim * Vdim;
#pragma unroll
        for (int j = 0; j < 8; j++) {
            hT[hb + (size_t)(kbase + 2 * j)     * Vdim + vcol] = s2[j].x;
            hT[hb + (size_t)(kbase + 2 * j + 1) * Vdim + vcol] = s2[j].y;
        }
    }
}

extern "C" void kernel_launch(void* const* d_in, const int* in_sizes, int n_in,
                              void* d_out, int out_size) {
    const float* r  = (const float*)d_in[0];
    const float* k  = (const float*)d_in[1];
    const float* v  = (const float*)d_in[2];
    const float* w  = (const float*)d_in[3];
    const float* u  = (const float*)d_in[4];
    const float* h0 = (const float*)d_in[5];

    float* o  = (float*)d_out;
    float* hT = o + (size_t)Bdim * Hdim * Tdim * Vdim;

    rwkv6_scan_kernel<<<Bdim * Hdim, 256>>>(r, k, v, w, u, h0, o, hT);
}